// round 14
// baseline (speedup 1.0000x reference)
#include <cuda_runtime.h>
#include <cuda.h>
#include <cuda_bf16.h>
#include <cuda_fp16.h>
#include <cstdint>

static constexpr int ENC_DIM = 640;
static constexpr int INNER   = 512;
static constexpr int VOCAB   = 2048;
static constexpr int BT      = 1024;
static constexpr int MROWS   = 65536;

__device__ float  g_P[BT * INNER];     // enc_proj + b1
__device__ float  g_Q[256 * INNER];    // dec_proj
__device__ __half g_H[(size_t)MROWS * INNER];   // tanh(...) in fp16 (67 MB)
__device__ __half g_W2r[VOCAB * INNER];         // W2 in fp16 (2 MB)

#if !defined(__CUDA_ARCH__) || defined(__CUDA_ARCH_FEAT_SM103_ALL) || defined(__CUDA_ARCH_FEAT_SM100_ALL) || defined(__CUDA_ARCH_FEAT_SM101_ALL)
#define HAS_TCGEN05 1
#else
#define HAS_TCGEN05 0
#endif

__device__ __forceinline__ uint32_t smem_to_u32(const void* ptr) {
    uint32_t a;
    asm("{ .reg .u64 t; cvta.to.shared.u64 t, %1; cvt.u32.u64 %0, t; }" : "=r"(a) : "l"(ptr));
    return a;
}
__device__ __forceinline__ float tanh_fast(float x) {
    float y;
    asm("tanh.approx.f32 %0, %1;" : "=f"(y) : "f"(x));
    return y;
}

#if HAS_TCGEN05
__device__ __forceinline__ uint32_t elect_one_pred() {
    uint32_t p;
    asm volatile("{\n\t.reg .pred p;\n\telect.sync _|p, 0xFFFFFFFF;\n\tselp.b32 %0, 1, 0, p;\n\t}" : "=r"(p));
    return p;
}
__device__ __forceinline__ uint32_t cluster_ctarank() {
    uint32_t r;
    asm("mov.u32 %0, %%cluster_ctarank;" : "=r"(r));
    return r;
}
#define MBARRIER_INIT(m, c) \
    asm volatile("mbarrier.init.shared.b64 [%0], %1;" :: "r"((uint32_t)(m)), "r"((uint32_t)(c)) : "memory")
#define MBARRIER_EXPECT_TX(m, b) \
    asm volatile("mbarrier.arrive.expect_tx.shared.b64 _, [%0], %1;" :: "r"((uint32_t)(m)), "r"((uint32_t)(b)) : "memory")
// arrive on the LEADER CTA's barrier at same offset (clear bit 24)
#define MBARRIER_ARRIVE_LEADER(m) \
    asm volatile("{\n\t.reg .b32 a;\n\tand.b32 a, %0, 0xFEFFFFFF;\n\tmbarrier.arrive.shared::cluster.b64 _, [a];\n\t}" \
        :: "r"((uint32_t)(m)) : "memory")

#define MBAR_WAIT(m, ph, SEM) do { \
    uint32_t _m = (uint32_t)(m); uint32_t _p = (uint32_t)(ph); uint32_t _d; \
    asm volatile("{\n\t.reg .pred p;\n\tmbarrier.try_wait.parity." SEM ".cta.shared::cta.b64 p, [%1], %2;\n\tselp.b32 %0, 1, 0, p;\n\t}" \
        : "=r"(_d) : "r"(_m), "r"(_p) : "memory"); \
    if (!_d) { \
        asm volatile("{\n\t.reg .pred P1;\n\tWL_%=:\n\tmbarrier.try_wait.parity." SEM ".cta.shared::cta.b64 P1, [%0], %1, 0x989680;\n\t@P1 bra.uni WD_%=;\n\tbra.uni WL_%=;\n\tWD_%=:\n\t}" \
            :: "r"(_m), "r"(_p) : "memory"); \
    } } while(0)
#define MBARRIER_WAIT_PARITY(m, p)          MBAR_WAIT(m, p, "acquire")
#define MBARRIER_WAIT_PARITY_RELAXED(m, p)  MBAR_WAIT(m, p, "relaxed")

#define TCGEN05_ALLOC_CG2(sa, n) \
    asm volatile("tcgen05.alloc.cta_group::2.sync.aligned.shared::cta.b32 [%0], %1;" :: "r"((uint32_t)(sa)), "r"((uint32_t)(n)) : "memory")
#define TCGEN05_DEALLOC_CG2(t, n) \
    asm volatile("tcgen05.dealloc.cta_group::2.sync.aligned.b32 %0, %1;" :: "r"(t), "r"((uint32_t)(n)))
#define TCGEN05_RELINQ_CG2() \
    asm volatile("tcgen05.relinquish_alloc_permit.cta_group::2.sync.aligned;")
#define TCGEN05_COMMIT_MC_CG2(m, mask) \
    asm volatile("tcgen05.commit.cta_group::2.mbarrier::arrive::one.shared::cluster.multicast::cluster.b64 [%0], %1;" \
        :: "r"((uint32_t)(m)), "h"((uint16_t)(mask)) : "memory")
#define TCGEN05_WAIT_LD()      asm volatile("tcgen05.wait::ld.sync.aligned;" ::: "memory")
#define TCGEN05_FENCE_AFTER()  asm volatile("tcgen05.fence::after_thread_sync;" ::: "memory")
#define TCGEN05_FENCE_BEFORE() asm volatile("tcgen05.fence::before_thread_sync;" ::: "memory")
#define CLUSTER_SYNC() do { \
    asm volatile("barrier.cluster.arrive.aligned;" ::: "memory"); \
    asm volatile("barrier.cluster.wait.aligned;" ::: "memory"); } while(0)

#define TCGEN05_LD_X32(r, ta) \
    asm volatile("tcgen05.ld.sync.aligned.32x32b.x32.b32 " \
        "{%0, %1, %2, %3, %4, %5, %6, %7, %8, %9, %10, %11, %12, %13, %14, %15, " \
        " %16, %17, %18, %19, %20, %21, %22, %23, %24, %25, %26, %27, %28, %29, %30, %31}, [%32];" \
        : "=r"((r)[0]), "=r"((r)[1]), "=r"((r)[2]), "=r"((r)[3]), "=r"((r)[4]), "=r"((r)[5]), "=r"((r)[6]), "=r"((r)[7]), \
          "=r"((r)[8]), "=r"((r)[9]), "=r"((r)[10]), "=r"((r)[11]), "=r"((r)[12]), "=r"((r)[13]), "=r"((r)[14]), "=r"((r)[15]), \
          "=r"((r)[16]), "=r"((r)[17]), "=r"((r)[18]), "=r"((r)[19]), "=r"((r)[20]), "=r"((r)[21]), "=r"((r)[22]), "=r"((r)[23]), \
          "=r"((r)[24]), "=r"((r)[25]), "=r"((r)[26]), "=r"((r)[27]), "=r"((r)[28]), "=r"((r)[29]), "=r"((r)[30]), "=r"((r)[31]) \
        : "r"(ta))

static constexpr uint64_t DESC_SW128 =
    (uint64_t(2) << 61) | (uint64_t(1) << 46) | (uint64_t(64) << 32) | (uint64_t(1) << 16);
#define MAKE_SMEM_DESC(a) (DESC_SW128 | ((uint64_t)((a) >> 4) & 0x3FFF))

// cta_group::2 TMA: both CTAs issue; complete_tx to the LEADER's barrier.
__device__ __forceinline__ void tma_load_2d_cg2(uint32_t sa, const void* map, int x, int y, uint32_t mbar) {
    asm volatile(
        "{\n\t.reg .b32 lb;\n\tand.b32 lb, %4, 0xFEFFFFFF;\n\t"
        "cp.async.bulk.tensor.2d.cta_group::2.shared::cluster.global.tile.mbarrier::complete_tx::bytes "
        "[%0], [%1, {%2, %3}], [lb];\n\t}"
        :: "r"(sa), "l"(map), "r"(x), "r"(y), "r"(mbar) : "memory");
}
__device__ __forceinline__ void mma_f16_ss_cg2(uint32_t d, uint64_t ad, uint64_t bd, uint32_t idesc, bool acc) {
    uint32_t en = acc ? 1u : 0u, z = 0;
    asm volatile("{\n\t.reg .pred p;\n\tsetp.ne.u32 p, %5, 0;\n\t"
                 "tcgen05.mma.cta_group::2.kind::f16 [%0], %1, %2, %3, {%4, %4, %4, %4, %4, %4, %4, %4}, p;\n\t}"
                 :: "r"(d), "l"(ad), "l"(bd), "r"(idesc), "r"(z), "r"(en) : "memory");
}
#endif // HAS_TCGEN05

// ============ K0: W2 -> fp16 copy ============
__global__ void round_w2_kernel(const float* __restrict__ W2) {
    int i = blockIdx.x * 256 + threadIdx.x;   // grid covers VOCAB*INNER/2
    float2 v = ((const float2*)W2)[i];
    ((__half2*)g_W2r)[i] = __floats2half2_rn(v.x, v.y);
}

// ============ K1: P = enc@We^T + b1, Q = dec@Wd^T ============
__global__ void proj_kernel(const float* __restrict__ enc, const float* __restrict__ dec,
                            const float* __restrict__ W1, const float* __restrict__ b1) {
    __shared__ float As[16][68];
    __shared__ float Bs[16][68];
    const int bn = blockIdx.x, bm = blockIdx.y;
    const int tid = threadIdx.x, tx = tid & 15, ty = tid >> 4;
    const bool is_enc = (bm < 16);
    const float* Asrc = is_enc ? (enc + (size_t)bm * 64 * ENC_DIM)
                               : (dec + (size_t)(bm - 16) * 64 * ENC_DIM);
    const int koff = is_enc ? 0 : ENC_DIM;
    float acc[4][4];
#pragma unroll
    for (int i = 0; i < 4; i++)
#pragma unroll
        for (int j = 0; j < 4; j++) acc[i][j] = 0.f;

    for (int kt = 0; kt < 40; kt++) {
#pragma unroll
        for (int p = 0; p < 4; p++) {
            int idx = tid + p * 256, m = idx >> 4, k = idx & 15;
            As[k][m] = Asrc[(size_t)m * ENC_DIM + kt * 16 + k];
            Bs[k][m] = W1[(size_t)(bn * 64 + m) * 1280 + koff + kt * 16 + k];
        }
        __syncthreads();
#pragma unroll
        for (int kk = 0; kk < 16; kk++) {
            float4 a = *(const float4*)&As[kk][ty * 4];
            float4 b = *(const float4*)&Bs[kk][tx * 4];
            float av[4] = {a.x, a.y, a.z, a.w}, bv[4] = {b.x, b.y, b.z, b.w};
#pragma unroll
            for (int i = 0; i < 4; i++)
#pragma unroll
                for (int j = 0; j < 4; j++) acc[i][j] += av[i] * bv[j];
        }
        __syncthreads();
    }
    float bias[4] = {0.f, 0.f, 0.f, 0.f};
    if (is_enc) {
#pragma unroll
        for (int j = 0; j < 4; j++) bias[j] = b1[bn * 64 + tx * 4 + j];
    }
#pragma unroll
    for (int i = 0; i < 4; i++) {
        int mg = bm * 64 + ty * 4 + i;
        float* dst = (mg < BT) ? &g_P[(size_t)mg * INNER] : &g_Q[(size_t)(mg - BT) * INNER];
        *(float4*)&dst[bn * 64 + tx * 4] = make_float4(acc[i][0] + bias[0], acc[i][1] + bias[1],
                                                       acc[i][2] + bias[2], acc[i][3] + bias[3]);
    }
}

// ============ K2: H = fp16(tanh(P + Q)) ============
__global__ void h_kernel() {
    __shared__ float4 sPB[128];
    const int bt = blockIdx.x, b = bt >> 8;
    if (threadIdx.x < 128)
        sPB[threadIdx.x] = ((const float4*)(g_P + (size_t)bt * INNER))[threadIdx.x];
    __syncthreads();
    const float4* Qb = (const float4*)(g_Q + (size_t)b * 64 * INNER);
    uint2* Hrow = (uint2*)(g_H + (size_t)bt * 64 * INNER);
#pragma unroll 4
    for (int i = threadIdx.x; i < 64 * 128; i += 256) {
        const float4 p = sPB[i & 127];
        const float4 q = Qb[i];
        __half2 h0 = __floats2half2_rn(tanh_fast(p.x + q.x), tanh_fast(p.y + q.y));
        __half2 h1 = __floats2half2_rn(tanh_fast(p.z + q.z), tanh_fast(p.w + q.w));
        uint2 u;
        u.x = *(uint32_t*)&h0;
        u.y = *(uint32_t*)&h1;
        Hrow[i] = u;
    }
}

// ==== K3: persistent cluster-2 cg2 fp16 GEMM; B resident in SMEM, A streamed =
static constexpr int KC = 64, NK = INNER / KC;           // 8 chunks per tile
static constexpr int STG = 4;                            // A stages
static constexpr int NCLUST = 64;                        // nn = cid>>3 (8 each)
static constexpr int TPC = 32;                           // m-tiles per cluster
static constexpr int THREADS = 192;
// kind::f16, fp16 inputs, fp32 accum, M=256 (cg2), N=256
static constexpr uint32_t IDESC_F16_CG2 =
    (1u << 4) | (32u << 17) | (16u << 24);

static constexpr int SM_TMEMP = 0;
static constexpr int SM_BINIT = 16;                     // one-shot B-resident barrier
static constexpr int SM_FULL  = 32;                     // full[s] = 32 + 16*s
static constexpr int SM_DONE  = 128;                    // done[s] = 128 + 16*s
static constexpr int SM_FINB  = 224;                    // fin[b]  = 224 + 16*b
static constexpr int SM_FREE  = 272;                    // free[b] = 272 + 16*b
static constexpr int SM_A     = 4096;
static constexpr int AB_BYTES = 128 * KC * 2;           // 16 KB (one K-chunk, one matrix)
static constexpr int SM_B     = SM_A + STG * AB_BYTES;  // 69632 (A: 64 KB)
static constexpr int B_BYTES  = NK * AB_BYTES;          // 128 KB resident B
static constexpr int SMEM_SZ  = SM_B + B_BYTES;         // 200704
static constexpr int TX_A     = 2 * AB_BYTES;           // 32 KB (both CTAs' A)
static constexpr int TX_B     = 2 * B_BYTES;            // 256 KB one-shot

__global__ void __launch_bounds__(THREADS, 1) __cluster_dims__(2, 1, 1) joint_gemm(
    const __grid_constant__ CUtensorMap tma_h,
    const __grid_constant__ CUtensorMap tma_w,
    const float* __restrict__ b2, float* __restrict__ out) {
    extern __shared__ __align__(1024) char smem[];
    const int tid = threadIdx.x;
    const int cid = blockIdx.x >> 1;
    const int nn = cid >> 3;                 // n-tile owned by this cluster
    const int mt0 = (cid & 7) * TPC;         // first m-tile
#if HAS_TCGEN05
    const uint32_t sb = smem_to_u32(smem);
    const int wid = tid >> 5, lid = tid & 31;
    const uint32_t rank = cluster_ctarank();

    if (tid == 0) {
        MBARRIER_INIT(sb + SM_BINIT, 1);
#pragma unroll
        for (int s = 0; s < STG; s++) {
            MBARRIER_INIT(sb + SM_FULL + 16 * s, 1);   // complete_tx only
            MBARRIER_INIT(sb + SM_DONE + 16 * s, 1);   // commit mcast 0x3
        }
#pragma unroll
        for (int b = 0; b < 2; b++) {
            MBARRIER_INIT(sb + SM_FINB + 16 * b, 1);
            MBARRIER_INIT(sb + SM_FREE + 16 * b, 2);   // both CTAs' epilogues
        }
    }
    if (wid == 0) { TCGEN05_ALLOC_CG2(sb + SM_TMEMP, 512); TCGEN05_RELINQ_CG2(); }
    __syncthreads();
    uint32_t tmem;
    asm volatile("ld.shared.b32 %0, [%1];" : "=r"(tmem) : "r"(sb + SM_TMEMP));
    CLUSTER_SYNC();   // peer barriers live before cg2 TMA / multicast commit

    const int gend = TPC * NK;   // 256 A chunks

    if (wid == 5) {
        // ===== producer (both CTAs, one elected thread) =====
        if (elect_one_pred()) {
            // one-shot: load resident B[nn] (8 chunks x 16 KB per CTA)
            if (rank == 0) MBARRIER_EXPECT_TX(sb + SM_BINIT, TX_B);
#pragma unroll
            for (int k = 0; k < NK; k++)
                tma_load_2d_cg2(sb + SM_B + k * AB_BYTES, &tma_w, k * KC,
                                nn * 256 + (int)rank * 128, sb + SM_BINIT);
            // steady state: stream A only
            int dph[STG] = {0, 0, 0, 0};
            for (int g = 0; g < gend; g++) {
                const int s = g & (STG - 1);
                if (g >= STG) { MBARRIER_WAIT_PARITY_RELAXED(sb + SM_DONE + 16 * s, dph[s]); dph[s] ^= 1; }
                const int mt = mt0 + (g >> 3);
                const int kc = g & 7;
                const uint32_t full = sb + SM_FULL + 16 * s;
                if (rank == 0) MBARRIER_EXPECT_TX(full, TX_A);
                tma_load_2d_cg2(sb + SM_A + s * AB_BYTES, &tma_h, kc * KC,
                                mt * 256 + (int)rank * 128, full);
            }
        }
    } else if (wid == 4) {
        // ===== MMA issuer (leader CTA only, one elected thread) =====
        if (rank == 0 && elect_one_pred()) {
            MBARRIER_WAIT_PARITY(sb + SM_BINIT, 0);   // resident B ready (both CTAs)
            int fph[STG] = {0, 0, 0, 0};
            int frph[2] = {0, 0};
            for (int ti = 0; ti < TPC; ti++) {
                const int b = ti & 1;
                if (ti >= 2) { MBARRIER_WAIT_PARITY(sb + SM_FREE + 16 * b, frph[b]); frph[b] ^= 1; }
                const uint32_t dbuf = tmem + b * 256;
                for (int kc = 0; kc < NK; kc++) {
                    const int s = (ti * NK + kc) & (STG - 1);
                    MBARRIER_WAIT_PARITY_RELAXED(sb + SM_FULL + 16 * s, fph[s]); fph[s] ^= 1;
                    const uint64_t ad = MAKE_SMEM_DESC(sb + SM_A + s * AB_BYTES);
                    const uint64_t bd = MAKE_SMEM_DESC(sb + SM_B + kc * AB_BYTES);
#pragma unroll
                    for (int j = 0; j < 4; j++)   // K=16 fp16 = 32B = 2 desc units
                        mma_f16_ss_cg2(dbuf, ad + 2 * j, bd + 2 * j, IDESC_F16_CG2, (kc | j) != 0);
                    TCGEN05_COMMIT_MC_CG2(sb + SM_DONE + 16 * s, 0x3);
                }
                TCGEN05_COMMIT_MC_CG2(sb + SM_FINB + 16 * b, 0x3);
            }
        }
    } else {
        // ===== epilogue (warps 0-3, both CTAs) =====
        const float4* b2v = (const float4*)b2;
        int finph[2] = {0, 0};
        for (int ti = 0; ti < TPC; ti++) {
            const int b = ti & 1;
            MBARRIER_WAIT_PARITY(sb + SM_FINB + 16 * b, finph[b]); finph[b] ^= 1;
            TCGEN05_FENCE_AFTER();
            const int mt = mt0 + ti;
            const int row = mt * 256 + (int)rank * 128 + wid * 32 + lid;
            float4* orow = (float4*)(out + (size_t)row * VOCAB + nn * 256);
            const uint32_t dbuf = tmem + b * 256;
#pragma unroll 1
            for (int ch = 0; ch < 8; ch++) {
                uint32_t r[32];
                TCGEN05_LD_X32(r, dbuf + ch * 32);
                TCGEN05_WAIT_LD();
#pragma unroll
                for (int j = 0; j < 8; j++) {
                    float4 bb = b2v[nn * 64 + ch * 8 + j];
                    float4 v;
                    v.x = __uint_as_float(r[j * 4 + 0]) + bb.x;
                    v.y = __uint_as_float(r[j * 4 + 1]) + bb.y;
                    v.z = __uint_as_float(r[j * 4 + 2]) + bb.z;
                    v.w = __uint_as_float(r[j * 4 + 3]) + bb.w;
                    orow[ch * 8 + j] = v;
                }
            }
            TCGEN05_FENCE_BEFORE();
            asm volatile("bar.sync 1, 128;" ::: "memory");   // warps 0-3 of this CTA
            if (tid == 0) MBARRIER_ARRIVE_LEADER(sb + SM_FREE + 16 * b);
        }
    }

    __syncthreads();
    if (wid == 0) TCGEN05_DEALLOC_CG2(tmem, 512);
    CLUSTER_SYNC();
#else
    // SIMT fallback (non-'a' target only): correct, never selected on GB300.
    (void)tma_h; (void)tma_w;
    const int rank = blockIdx.x & 1;
    for (int ti = 0; ti < TPC; ti++) {
        const int mt = mt0 + ti;
        for (int e = tid; e < 128 * 256; e += THREADS) {
            const int r = e >> 8, c = e & 255;
            const int row = mt * 256 + rank * 128 + r;
            const __half* Ar = &g_H[(size_t)row * INNER];
            const __half* Br = &g_W2r[(size_t)(nn * 256 + c) * INNER];
            float acc = 0.f;
            for (int k = 0; k < INNER; k++) acc += __half2float(Ar[k]) * __half2float(Br[k]);
            out[(size_t)row * VOCAB + nn * 256 + c] = acc + b2[nn * 256 + c];
        }
    }
#endif
}

// ============ host ============
typedef CUresult (*PFN_encodeTiled)(
    CUtensorMap*, CUtensorMapDataType, cuuint32_t, void*,
    const cuuint64_t*, const cuuint64_t*, const cuuint32_t*, const cuuint32_t*,
    CUtensorMapInterleave, CUtensorMapSwizzle, CUtensorMapL2promotion, CUtensorMapFloatOOBfill);

static void make_map_f16(PFN_encodeTiled fn, CUtensorMap* m, void* ptr,
                         uint64_t d0, uint64_t d1, uint32_t b0, uint32_t b1) {
    cuuint64_t dims[2] = {d0, d1};
    cuuint64_t strides[1] = {d0 * 2};
    cuuint32_t box[2] = {b0, b1};
    cuuint32_t es[2] = {1, 1};
    fn(m, CU_TENSOR_MAP_DATA_TYPE_FLOAT16, 2, ptr, dims, strides, box, es,
       CU_TENSOR_MAP_INTERLEAVE_NONE, CU_TENSOR_MAP_SWIZZLE_128B,
       CU_TENSOR_MAP_L2_PROMOTION_L2_128B, CU_TENSOR_MAP_FLOAT_OOB_FILL_NONE);
}

extern "C" void kernel_launch(void* const* d_in, const int* in_sizes, int n_in,
                              void* d_out, int out_size) {
    const float* enc = (const float*)d_in[0];
    const float* dec = (const float*)d_in[1];
    const float* W1  = (const float*)d_in[2];
    const float* b1  = (const float*)d_in[3];
    const float* W2  = (const float*)d_in[4];
    const float* b2  = (const float*)d_in[5];
    float* out = (float*)d_out;

    void* hptr = nullptr; cudaGetSymbolAddress(&hptr, g_H);
    void* wptr = nullptr; cudaGetSymbolAddress(&wptr, g_W2r);

    PFN_encodeTiled enc_fn = nullptr;
    cudaDriverEntryPointQueryResult st;
    cudaGetDriverEntryPointByVersion("cuTensorMapEncodeTiled", (void**)&enc_fn, 12050,
                                     cudaEnableDefault, &st);
    CUtensorMap mapH, mapW;
    make_map_f16(enc_fn, &mapH, hptr, INNER, MROWS, KC, 128);
    make_map_f16(enc_fn, &mapW, wptr, INNER, VOCAB, KC, 128);

    cudaFuncSetAttribute(joint_gemm, cudaFuncAttributeMaxDynamicSharedMemorySize, SMEM_SZ);

    round_w2_kernel<<<VOCAB * INNER / 512, 256>>>(W2);
    proj_kernel<<<dim3(8, 20), 256>>>(enc, dec, W1, b1);
    h_kernel<<<BT, 256>>>();
    joint_gemm<<<NCLUST * 2, THREADS, SMEM_SZ>>>(mapH, mapW, b2, out);
}

// round 15
// speedup vs baseline: 1.0518x; 1.0518x over previous
#include <cuda_runtime.h>
#include <cuda.h>
#include <cuda_bf16.h>
#include <cuda_fp16.h>
#include <cstdint>

static constexpr int ENC_DIM = 640;
static constexpr int INNER   = 512;
static constexpr int VOCAB   = 2048;
static constexpr int BT      = 1024;
static constexpr int MROWS   = 65536;

__device__ float  g_P[BT * INNER];     // enc_proj + b1
__device__ float  g_Q[256 * INNER];    // dec_proj
__device__ __half g_H[(size_t)MROWS * INNER];   // tanh(...) in fp16 (67 MB)
__device__ __half g_W2r[VOCAB * INNER];         // W2 in fp16 (2 MB)

#if !defined(__CUDA_ARCH__) || defined(__CUDA_ARCH_FEAT_SM103_ALL) || defined(__CUDA_ARCH_FEAT_SM100_ALL) || defined(__CUDA_ARCH_FEAT_SM101_ALL)
#define HAS_TCGEN05 1
#else
#define HAS_TCGEN05 0
#endif

__device__ __forceinline__ uint32_t smem_to_u32(const void* ptr) {
    uint32_t a;
    asm("{ .reg .u64 t; cvta.to.shared.u64 t, %1; cvt.u32.u64 %0, t; }" : "=r"(a) : "l"(ptr));
    return a;
}
__device__ __forceinline__ float tanh_fast(float x) {
    float y;
    asm("tanh.approx.f32 %0, %1;" : "=f"(y) : "f"(x));
    return y;
}

#if HAS_TCGEN05
__device__ __forceinline__ uint32_t elect_one_pred() {
    uint32_t p;
    asm volatile("{\n\t.reg .pred p;\n\telect.sync _|p, 0xFFFFFFFF;\n\tselp.b32 %0, 1, 0, p;\n\t}" : "=r"(p));
    return p;
}
__device__ __forceinline__ uint32_t cluster_ctarank() {
    uint32_t r;
    asm("mov.u32 %0, %%cluster_ctarank;" : "=r"(r));
    return r;
}
#define MBARRIER_INIT(m, c) \
    asm volatile("mbarrier.init.shared.b64 [%0], %1;" :: "r"((uint32_t)(m)), "r"((uint32_t)(c)) : "memory")
#define MBARRIER_EXPECT_TX(m, b) \
    asm volatile("mbarrier.arrive.expect_tx.shared.b64 _, [%0], %1;" :: "r"((uint32_t)(m)), "r"((uint32_t)(b)) : "memory")
// arrive on the LEADER CTA's barrier at same offset (clear bit 24)
#define MBARRIER_ARRIVE_LEADER(m) \
    asm volatile("{\n\t.reg .b32 a;\n\tand.b32 a, %0, 0xFEFFFFFF;\n\tmbarrier.arrive.shared::cluster.b64 _, [a];\n\t}" \
        :: "r"((uint32_t)(m)) : "memory")

#define MBAR_WAIT(m, ph, SEM) do { \
    uint32_t _m = (uint32_t)(m); uint32_t _p = (uint32_t)(ph); uint32_t _d; \
    asm volatile("{\n\t.reg .pred p;\n\tmbarrier.try_wait.parity." SEM ".cta.shared::cta.b64 p, [%1], %2;\n\tselp.b32 %0, 1, 0, p;\n\t}" \
        : "=r"(_d) : "r"(_m), "r"(_p) : "memory"); \
    if (!_d) { \
        asm volatile("{\n\t.reg .pred P1;\n\tWL_%=:\n\tmbarrier.try_wait.parity." SEM ".cta.shared::cta.b64 P1, [%0], %1, 0x989680;\n\t@P1 bra.uni WD_%=;\n\tbra.uni WL_%=;\n\tWD_%=:\n\t}" \
            :: "r"(_m), "r"(_p) : "memory"); \
    } } while(0)
#define MBARRIER_WAIT_PARITY(m, p)          MBAR_WAIT(m, p, "acquire")
#define MBARRIER_WAIT_PARITY_RELAXED(m, p)  MBAR_WAIT(m, p, "relaxed")

#define TCGEN05_ALLOC_CG2(sa, n) \
    asm volatile("tcgen05.alloc.cta_group::2.sync.aligned.shared::cta.b32 [%0], %1;" :: "r"((uint32_t)(sa)), "r"((uint32_t)(n)) : "memory")
#define TCGEN05_DEALLOC_CG2(t, n) \
    asm volatile("tcgen05.dealloc.cta_group::2.sync.aligned.b32 %0, %1;" :: "r"(t), "r"((uint32_t)(n)))
#define TCGEN05_RELINQ_CG2() \
    asm volatile("tcgen05.relinquish_alloc_permit.cta_group::2.sync.aligned;")
#define TCGEN05_COMMIT_MC_CG2(m, mask) \
    asm volatile("tcgen05.commit.cta_group::2.mbarrier::arrive::one.shared::cluster.multicast::cluster.b64 [%0], %1;" \
        :: "r"((uint32_t)(m)), "h"((uint16_t)(mask)) : "memory")
#define TCGEN05_WAIT_LD()      asm volatile("tcgen05.wait::ld.sync.aligned;" ::: "memory")
#define TCGEN05_FENCE_AFTER()  asm volatile("tcgen05.fence::after_thread_sync;" ::: "memory")
#define TCGEN05_FENCE_BEFORE() asm volatile("tcgen05.fence::before_thread_sync;" ::: "memory")
#define CLUSTER_SYNC() do { \
    asm volatile("barrier.cluster.arrive.aligned;" ::: "memory"); \
    asm volatile("barrier.cluster.wait.aligned;" ::: "memory"); } while(0)

#define TCGEN05_LD_X32(r, ta) \
    asm volatile("tcgen05.ld.sync.aligned.32x32b.x32.b32 " \
        "{%0, %1, %2, %3, %4, %5, %6, %7, %8, %9, %10, %11, %12, %13, %14, %15, " \
        " %16, %17, %18, %19, %20, %21, %22, %23, %24, %25, %26, %27, %28, %29, %30, %31}, [%32];" \
        : "=r"((r)[0]), "=r"((r)[1]), "=r"((r)[2]), "=r"((r)[3]), "=r"((r)[4]), "=r"((r)[5]), "=r"((r)[6]), "=r"((r)[7]), \
          "=r"((r)[8]), "=r"((r)[9]), "=r"((r)[10]), "=r"((r)[11]), "=r"((r)[12]), "=r"((r)[13]), "=r"((r)[14]), "=r"((r)[15]), \
          "=r"((r)[16]), "=r"((r)[17]), "=r"((r)[18]), "=r"((r)[19]), "=r"((r)[20]), "=r"((r)[21]), "=r"((r)[22]), "=r"((r)[23]), \
          "=r"((r)[24]), "=r"((r)[25]), "=r"((r)[26]), "=r"((r)[27]), "=r"((r)[28]), "=r"((r)[29]), "=r"((r)[30]), "=r"((r)[31]) \
        : "r"(ta))

static constexpr uint64_t DESC_SW128 =
    (uint64_t(2) << 61) | (uint64_t(1) << 46) | (uint64_t(64) << 32) | (uint64_t(1) << 16);
#define MAKE_SMEM_DESC(a) (DESC_SW128 | ((uint64_t)((a) >> 4) & 0x3FFF))

// cta_group::2 TMA: both CTAs issue; complete_tx to the LEADER's barrier.
__device__ __forceinline__ void tma_load_2d_cg2(uint32_t sa, const void* map, int x, int y, uint32_t mbar) {
    asm volatile(
        "{\n\t.reg .b32 lb;\n\tand.b32 lb, %4, 0xFEFFFFFF;\n\t"
        "cp.async.bulk.tensor.2d.cta_group::2.shared::cluster.global.tile.mbarrier::complete_tx::bytes "
        "[%0], [%1, {%2, %3}], [lb];\n\t}"
        :: "r"(sa), "l"(map), "r"(x), "r"(y), "r"(mbar) : "memory");
}
__device__ __forceinline__ void mma_f16_ss_cg2(uint32_t d, uint64_t ad, uint64_t bd, uint32_t idesc, bool acc) {
    uint32_t en = acc ? 1u : 0u, z = 0;
    asm volatile("{\n\t.reg .pred p;\n\tsetp.ne.u32 p, %5, 0;\n\t"
                 "tcgen05.mma.cta_group::2.kind::f16 [%0], %1, %2, %3, {%4, %4, %4, %4, %4, %4, %4, %4}, p;\n\t}"
                 :: "r"(d), "l"(ad), "l"(bd), "r"(idesc), "r"(z), "r"(en) : "memory");
}
#endif // HAS_TCGEN05

// ============ K0: W2 -> fp16 copy ============
__global__ void round_w2_kernel(const float* __restrict__ W2) {
    int i = blockIdx.x * 256 + threadIdx.x;   // grid covers VOCAB*INNER/2
    float2 v = ((const float2*)W2)[i];
    ((__half2*)g_W2r)[i] = __floats2half2_rn(v.x, v.y);
}

// ============ K1: P = enc@We^T + b1, Q = dec@Wd^T ============
__global__ void proj_kernel(const float* __restrict__ enc, const float* __restrict__ dec,
                            const float* __restrict__ W1, const float* __restrict__ b1) {
    __shared__ float As[16][68];
    __shared__ float Bs[16][68];
    const int bn = blockIdx.x, bm = blockIdx.y;
    const int tid = threadIdx.x, tx = tid & 15, ty = tid >> 4;
    const bool is_enc = (bm < 16);
    const float* Asrc = is_enc ? (enc + (size_t)bm * 64 * ENC_DIM)
                               : (dec + (size_t)(bm - 16) * 64 * ENC_DIM);
    const int koff = is_enc ? 0 : ENC_DIM;
    float acc[4][4];
#pragma unroll
    for (int i = 0; i < 4; i++)
#pragma unroll
        for (int j = 0; j < 4; j++) acc[i][j] = 0.f;

    for (int kt = 0; kt < 40; kt++) {
#pragma unroll
        for (int p = 0; p < 4; p++) {
            int idx = tid + p * 256, m = idx >> 4, k = idx & 15;
            As[k][m] = Asrc[(size_t)m * ENC_DIM + kt * 16 + k];
            Bs[k][m] = W1[(size_t)(bn * 64 + m) * 1280 + koff + kt * 16 + k];
        }
        __syncthreads();
#pragma unroll
        for (int kk = 0; kk < 16; kk++) {
            float4 a = *(const float4*)&As[kk][ty * 4];
            float4 b = *(const float4*)&Bs[kk][tx * 4];
            float av[4] = {a.x, a.y, a.z, a.w}, bv[4] = {b.x, b.y, b.z, b.w};
#pragma unroll
            for (int i = 0; i < 4; i++)
#pragma unroll
                for (int j = 0; j < 4; j++) acc[i][j] += av[i] * bv[j];
        }
        __syncthreads();
    }
    float bias[4] = {0.f, 0.f, 0.f, 0.f};
    if (is_enc) {
#pragma unroll
        for (int j = 0; j < 4; j++) bias[j] = b1[bn * 64 + tx * 4 + j];
    }
#pragma unroll
    for (int i = 0; i < 4; i++) {
        int mg = bm * 64 + ty * 4 + i;
        float* dst = (mg < BT) ? &g_P[(size_t)mg * INNER] : &g_Q[(size_t)(mg - BT) * INNER];
        *(float4*)&dst[bn * 64 + tx * 4] = make_float4(acc[i][0] + bias[0], acc[i][1] + bias[1],
                                                       acc[i][2] + bias[2], acc[i][3] + bias[3]);
    }
}

// ============ K2: H = fp16(tanh(P + Q)) ============
__global__ void h_kernel() {
    __shared__ float4 sPB[128];
    const int bt = blockIdx.x, b = bt >> 8;
    if (threadIdx.x < 128)
        sPB[threadIdx.x] = ((const float4*)(g_P + (size_t)bt * INNER))[threadIdx.x];
    __syncthreads();
    const float4* Qb = (const float4*)(g_Q + (size_t)b * 64 * INNER);
    uint2* Hrow = (uint2*)(g_H + (size_t)bt * 64 * INNER);
#pragma unroll 4
    for (int i = threadIdx.x; i < 64 * 128; i += 256) {
        const float4 p = sPB[i & 127];
        const float4 q = Qb[i];
        __half2 h0 = __floats2half2_rn(tanh_fast(p.x + q.x), tanh_fast(p.y + q.y));
        __half2 h1 = __floats2half2_rn(tanh_fast(p.z + q.z), tanh_fast(p.w + q.w));
        uint2 u;
        u.x = *(uint32_t*)&h0;
        u.y = *(uint32_t*)&h1;
        Hrow[i] = u;
    }
}

// ==== K3: persistent cluster-2 cg2 fp16 GEMM, K=128 super-chunks, STG=3 ======
static constexpr int KC = 64;                            // TMA box width (128B SW128)
static constexpr int KSC = 128;                          // K per super-chunk
static constexpr int NKS = INNER / KSC;                  // 4 super-chunks per tile
static constexpr int STG = 3;
static constexpr int TILES_N = VOCAB / 256;              // 8
static constexpr int TOTAL_TILES = (MROWS / 256) * TILES_N;  // 2048
static constexpr int NCLUST = 74;
static constexpr int TPC = (TOTAL_TILES + NCLUST - 1) / NCLUST;  // 28
static constexpr int THREADS = 192;
// kind::f16, fp16 inputs, fp32 accum, M=256 (cg2), N=256
static constexpr uint32_t IDESC_F16_CG2 =
    (1u << 4) | (32u << 17) | (16u << 24);

static constexpr int SM_TMEMP = 0;
static constexpr int SM_FULL  = 32;                     // full[s] = 32 + 16*s (3)
static constexpr int SM_DONE  = 128;                    // done[s] = 128 + 16*s (3)
static constexpr int SM_FINB  = 224;                    // fin[b]  = 224 + 16*b
static constexpr int SM_FREE  = 272;                    // free[b] = 272 + 16*b
static constexpr int SM_A     = 4096;
static constexpr int SUB_B    = 16384;                  // 128 rows x 64 fp16
static constexpr int STAGE_B  = 4 * SUB_B;              // A0,A1,B0,B1 = 64 KB
static constexpr int SMEM_SZ  = SM_A + STG * STAGE_B;   // 200704
static constexpr int TX_BYTES = 2 * STAGE_B;            // 128 KB (both CTAs)

__global__ void __launch_bounds__(THREADS, 1) __cluster_dims__(2, 1, 1) joint_gemm(
    const __grid_constant__ CUtensorMap tma_h,
    const __grid_constant__ CUtensorMap tma_w,
    const float* __restrict__ b2, float* __restrict__ out) {
    extern __shared__ __align__(1024) char smem[];
    const int tid = threadIdx.x;
    const int cid = blockIdx.x >> 1;
    const int first = cid * TPC;
    const int nt = min(TPC, TOTAL_TILES - first);
#if HAS_TCGEN05
    const uint32_t sb = smem_to_u32(smem);
    const int wid = tid >> 5, lid = tid & 31;
    const uint32_t rank = cluster_ctarank();

    if (tid == 0) {
#pragma unroll
        for (int s = 0; s < STG; s++) {
            MBARRIER_INIT(sb + SM_FULL + 16 * s, 1);   // complete_tx only
            MBARRIER_INIT(sb + SM_DONE + 16 * s, 1);   // commit mcast 0x3
        }
#pragma unroll
        for (int b = 0; b < 2; b++) {
            MBARRIER_INIT(sb + SM_FINB + 16 * b, 1);
            MBARRIER_INIT(sb + SM_FREE + 16 * b, 2);   // both CTAs' epilogues
        }
    }
    if (wid == 0) { TCGEN05_ALLOC_CG2(sb + SM_TMEMP, 512); TCGEN05_RELINQ_CG2(); }
    __syncthreads();
    uint32_t tmem;
    asm volatile("ld.shared.b32 %0, [%1];" : "=r"(tmem) : "r"(sb + SM_TMEMP));
    CLUSTER_SYNC();   // peer barriers live before cg2 TMA / multicast commit

    const int gend = nt * NKS;   // super-chunks total

    if (wid == 5) {
        // ===== producer (both CTAs, one elected thread) =====
        if (elect_one_pred()) {
            int dph[STG] = {0, 0, 0};
            int s = 0;
            for (int g = 0; g < gend; g++) {
                if (g >= STG) { MBARRIER_WAIT_PARITY_RELAXED(sb + SM_DONE + 16 * s, dph[s]); dph[s] ^= 1; }
                const int t = first + (g >> 2);
                const int ks = g & 3;                  // super-chunk index
                const int nn = t & 7, mt = t >> 3;
                const uint32_t full = sb + SM_FULL + 16 * s;
                const uint32_t stg = sb + SM_A + s * STAGE_B;
                if (rank == 0) MBARRIER_EXPECT_TX(full, TX_BYTES);
                const int arow = mt * 256 + (int)rank * 128;
                const int brow = nn * 256 + (int)rank * 128;
                tma_load_2d_cg2(stg,             &tma_h, ks * KSC,      arow, full);
                tma_load_2d_cg2(stg + SUB_B,     &tma_h, ks * KSC + KC, arow, full);
                tma_load_2d_cg2(stg + 2 * SUB_B, &tma_w, ks * KSC,      brow, full);
                tma_load_2d_cg2(stg + 3 * SUB_B, &tma_w, ks * KSC + KC, brow, full);
                if (++s == STG) s = 0;
            }
        }
    } else if (wid == 4) {
        // ===== MMA issuer (leader CTA only, one elected thread) =====
        if (rank == 0 && elect_one_pred()) {
            int fph[STG] = {0, 0, 0};
            int frph[2] = {0, 0};
            int s = 0;
            for (int g = 0; g < gend; g++) {
                const int ks = g & 3;
                const int ti = g >> 2;
                const int b = ti & 1;
                if (ks == 0 && ti >= 2) {
                    MBARRIER_WAIT_PARITY(sb + SM_FREE + 16 * b, frph[b]); frph[b] ^= 1;
                }
                MBARRIER_WAIT_PARITY_RELAXED(sb + SM_FULL + 16 * s, fph[s]); fph[s] ^= 1;
                const uint32_t dbuf = tmem + b * 256;
                const uint32_t stg = sb + SM_A + s * STAGE_B;
#pragma unroll
                for (int h = 0; h < 2; h++) {
                    const uint64_t ad = MAKE_SMEM_DESC(stg + h * SUB_B);
                    const uint64_t bd = MAKE_SMEM_DESC(stg + (2 + h) * SUB_B);
#pragma unroll
                    for (int j = 0; j < 4; j++)   // K=16 fp16 = 32B = 2 desc units
                        mma_f16_ss_cg2(dbuf, ad + 2 * j, bd + 2 * j, IDESC_F16_CG2,
                                       (ks | h | j) != 0);
                }
                TCGEN05_COMMIT_MC_CG2(sb + SM_DONE + 16 * s, 0x3);
                if (ks == 3) TCGEN05_COMMIT_MC_CG2(sb + SM_FINB + 16 * b, 0x3);
                if (++s == STG) s = 0;
            }
        }
    } else {
        // ===== epilogue (warps 0-3, both CTAs) =====
        const float4* b2v = (const float4*)b2;
        int finph[2] = {0, 0};
        for (int ti = 0; ti < nt; ti++) {
            const int b = ti & 1;
            MBARRIER_WAIT_PARITY(sb + SM_FINB + 16 * b, finph[b]); finph[b] ^= 1;
            TCGEN05_FENCE_AFTER();
            const int t = first + ti;
            const int nn = t & 7, mt = t >> 3;
            const int row = mt * 256 + (int)rank * 128 + wid * 32 + lid;
            float4* orow = (float4*)(out + (size_t)row * VOCAB + nn * 256);
            const uint32_t dbuf = tmem + b * 256;
#pragma unroll 1
            for (int ch = 0; ch < 8; ch++) {
                uint32_t r[32];
                TCGEN05_LD_X32(r, dbuf + ch * 32);
                TCGEN05_WAIT_LD();
#pragma unroll
                for (int j = 0; j < 8; j++) {
                    float4 bb = b2v[nn * 64 + ch * 8 + j];
                    float4 v;
                    v.x = __uint_as_float(r[j * 4 + 0]) + bb.x;
                    v.y = __uint_as_float(r[j * 4 + 1]) + bb.y;
                    v.z = __uint_as_float(r[j * 4 + 2]) + bb.z;
                    v.w = __uint_as_float(r[j * 4 + 3]) + bb.w;
                    orow[ch * 8 + j] = v;
                }
            }
            TCGEN05_FENCE_BEFORE();
            asm volatile("bar.sync 1, 128;" ::: "memory");   // warps 0-3 of this CTA
            if (tid == 0) MBARRIER_ARRIVE_LEADER(sb + SM_FREE + 16 * b);
        }
    }

    __syncthreads();
    if (wid == 0) TCGEN05_DEALLOC_CG2(tmem, 512);
    CLUSTER_SYNC();
#else
    // SIMT fallback (non-'a' target only): correct, never selected on GB300.
    (void)tma_h; (void)tma_w;
    const int rank = blockIdx.x & 1;
    for (int ti = 0; ti < nt; ti++) {
        const int t = first + ti;
        const int nn = t & 7, mt = t >> 3;
        for (int e = tid; e < 128 * 256; e += THREADS) {
            const int r = e >> 8, c = e & 255;
            const int row = mt * 256 + rank * 128 + r;
            const __half* Ar = &g_H[(size_t)row * INNER];
            const __half* Br = &g_W2r[(size_t)(nn * 256 + c) * INNER];
            float acc = 0.f;
            for (int k = 0; k < INNER; k++) acc += __half2float(Ar[k]) * __half2float(Br[k]);
            out[(size_t)row * VOCAB + nn * 256 + c] = acc + b2[nn * 256 + c];
        }
    }
#endif
}

// ============ host ============
typedef CUresult (*PFN_encodeTiled)(
    CUtensorMap*, CUtensorMapDataType, cuuint32_t, void*,
    const cuuint64_t*, const cuuint64_t*, const cuuint32_t*, const cuuint32_t*,
    CUtensorMapInterleave, CUtensorMapSwizzle, CUtensorMapL2promotion, CUtensorMapFloatOOBfill);

static void make_map_f16(PFN_encodeTiled fn, CUtensorMap* m, void* ptr,
                         uint64_t d0, uint64_t d1, uint32_t b0, uint32_t b1) {
    cuuint64_t dims[2] = {d0, d1};
    cuuint64_t strides[1] = {d0 * 2};
    cuuint32_t box[2] = {b0, b1};
    cuuint32_t es[2] = {1, 1};
    fn(m, CU_TENSOR_MAP_DATA_TYPE_FLOAT16, 2, ptr, dims, strides, box, es,
       CU_TENSOR_MAP_INTERLEAVE_NONE, CU_TENSOR_MAP_SWIZZLE_128B,
       CU_TENSOR_MAP_L2_PROMOTION_L2_128B, CU_TENSOR_MAP_FLOAT_OOB_FILL_NONE);
}

extern "C" void kernel_launch(void* const* d_in, const int* in_sizes, int n_in,
                              void* d_out, int out_size) {
    const float* enc = (const float*)d_in[0];
    const float* dec = (const float*)d_in[1];
    const float* W1  = (const float*)d_in[2];
    const float* b1  = (const float*)d_in[3];
    const float* W2  = (const float*)d_in[4];
    const float* b2  = (const float*)d_in[5];
    float* out = (float*)d_out;

    void* hptr = nullptr; cudaGetSymbolAddress(&hptr, g_H);
    void* wptr = nullptr; cudaGetSymbolAddress(&wptr, g_W2r);

    PFN_encodeTiled enc_fn = nullptr;
    cudaDriverEntryPointQueryResult st;
    cudaGetDriverEntryPointByVersion("cuTensorMapEncodeTiled", (void**)&enc_fn, 12050,
                                     cudaEnableDefault, &st);
    CUtensorMap mapH, mapW;
    make_map_f16(enc_fn, &mapH, hptr, INNER, MROWS, KC, 128);
    make_map_f16(enc_fn, &mapW, wptr, INNER, VOCAB, KC, 128);

    cudaFuncSetAttribute(joint_gemm, cudaFuncAttributeMaxDynamicSharedMemorySize, SMEM_SZ);

    round_w2_kernel<<<VOCAB * INNER / 512, 256>>>(W2);
    proj_kernel<<<dim3(8, 20), 256>>>(enc, dec, W1, b1);
    h_kernel<<<BT, 256>>>();
    joint_gemm<<<NCLUST * 2, THREADS, SMEM_SZ>>>(mapH, mapW, b2, out);
}

// round 16
// speedup vs baseline: 1.5012x; 1.4273x over previous
#include <cuda_runtime.h>
#include <cuda.h>
#include <cuda_bf16.h>
#include <cuda_fp16.h>
#include <cstdint>

static constexpr int ENC_DIM = 640;
static constexpr int INNER   = 512;
static constexpr int VOCAB   = 2048;
static constexpr int BT      = 1024;
static constexpr int MROWS   = 65536;

__device__ float  g_P[BT * INNER];     // enc_proj + b1
__device__ float  g_Q[256 * INNER];    // dec_proj
__device__ __half g_H[(size_t)MROWS * INNER];   // tanh(...) in fp16 (67 MB)
__device__ __half g_W2r[VOCAB * INNER];         // W2 in fp16 (2 MB)

#if !defined(__CUDA_ARCH__) || defined(__CUDA_ARCH_FEAT_SM103_ALL) || defined(__CUDA_ARCH_FEAT_SM100_ALL) || defined(__CUDA_ARCH_FEAT_SM101_ALL)
#define HAS_TCGEN05 1
#else
#define HAS_TCGEN05 0
#endif

__device__ __forceinline__ uint32_t smem_to_u32(const void* ptr) {
    uint32_t a;
    asm("{ .reg .u64 t; cvta.to.shared.u64 t, %1; cvt.u32.u64 %0, t; }" : "=r"(a) : "l"(ptr));
    return a;
}
__device__ __forceinline__ float tanh_fast(float x) {
    float y;
    asm("tanh.approx.f32 %0, %1;" : "=f"(y) : "f"(x));
    return y;
}

#if HAS_TCGEN05
__device__ __forceinline__ uint32_t elect_one_pred() {
    uint32_t p;
    asm volatile("{\n\t.reg .pred p;\n\telect.sync _|p, 0xFFFFFFFF;\n\tselp.b32 %0, 1, 0, p;\n\t}" : "=r"(p));
    return p;
}
__device__ __forceinline__ uint32_t cluster_ctarank() {
    uint32_t r;
    asm("mov.u32 %0, %%cluster_ctarank;" : "=r"(r));
    return r;
}
#define MBARRIER_INIT(m, c) \
    asm volatile("mbarrier.init.shared.b64 [%0], %1;" :: "r"((uint32_t)(m)), "r"((uint32_t)(c)) : "memory")
#define MBARRIER_EXPECT_TX(m, b) \
    asm volatile("mbarrier.arrive.expect_tx.shared.b64 _, [%0], %1;" :: "r"((uint32_t)(m)), "r"((uint32_t)(b)) : "memory")
// arrive on the LEADER CTA's barrier at same offset (clear bit 24)
#define MBARRIER_ARRIVE_LEADER(m) \
    asm volatile("{\n\t.reg .b32 a;\n\tand.b32 a, %0, 0xFEFFFFFF;\n\tmbarrier.arrive.shared::cluster.b64 _, [a];\n\t}" \
        :: "r"((uint32_t)(m)) : "memory")

#define MBAR_WAIT(m, ph, SEM) do { \
    uint32_t _m = (uint32_t)(m); uint32_t _p = (uint32_t)(ph); uint32_t _d; \
    asm volatile("{\n\t.reg .pred p;\n\tmbarrier.try_wait.parity." SEM ".cta.shared::cta.b64 p, [%1], %2;\n\tselp.b32 %0, 1, 0, p;\n\t}" \
        : "=r"(_d) : "r"(_m), "r"(_p) : "memory"); \
    if (!_d) { \
        asm volatile("{\n\t.reg .pred P1;\n\tWL_%=:\n\tmbarrier.try_wait.parity." SEM ".cta.shared::cta.b64 P1, [%0], %1, 0x989680;\n\t@P1 bra.uni WD_%=;\n\tbra.uni WL_%=;\n\tWD_%=:\n\t}" \
            :: "r"(_m), "r"(_p) : "memory"); \
    } } while(0)
#define MBARRIER_WAIT_PARITY(m, p)          MBAR_WAIT(m, p, "acquire")
#define MBARRIER_WAIT_PARITY_RELAXED(m, p)  MBAR_WAIT(m, p, "relaxed")

#define TCGEN05_ALLOC_CG2(sa, n) \
    asm volatile("tcgen05.alloc.cta_group::2.sync.aligned.shared::cta.b32 [%0], %1;" :: "r"((uint32_t)(sa)), "r"((uint32_t)(n)) : "memory")
#define TCGEN05_DEALLOC_CG2(t, n) \
    asm volatile("tcgen05.dealloc.cta_group::2.sync.aligned.b32 %0, %1;" :: "r"(t), "r"((uint32_t)(n)))
#define TCGEN05_RELINQ_CG2() \
    asm volatile("tcgen05.relinquish_alloc_permit.cta_group::2.sync.aligned;")
#define TCGEN05_COMMIT_MC_CG2(m, mask) \
    asm volatile("tcgen05.commit.cta_group::2.mbarrier::arrive::one.shared::cluster.multicast::cluster.b64 [%0], %1;" \
        :: "r"((uint32_t)(m)), "h"((uint16_t)(mask)) : "memory")
#define TCGEN05_WAIT_LD()      asm volatile("tcgen05.wait::ld.sync.aligned;" ::: "memory")
#define TCGEN05_FENCE_AFTER()  asm volatile("tcgen05.fence::after_thread_sync;" ::: "memory")
#define TCGEN05_FENCE_BEFORE() asm volatile("tcgen05.fence::before_thread_sync;" ::: "memory")
#define CLUSTER_SYNC() do { \
    asm volatile("barrier.cluster.arrive.aligned;" ::: "memory"); \
    asm volatile("barrier.cluster.wait.aligned;" ::: "memory"); } while(0)

#define TCGEN05_LD_X32(r, ta) \
    asm volatile("tcgen05.ld.sync.aligned.32x32b.x32.b32 " \
        "{%0, %1, %2, %3, %4, %5, %6, %7, %8, %9, %10, %11, %12, %13, %14, %15, " \
        " %16, %17, %18, %19, %20, %21, %22, %23, %24, %25, %26, %27, %28, %29, %30, %31}, [%32];" \
        : "=r"((r)[0]), "=r"((r)[1]), "=r"((r)[2]), "=r"((r)[3]), "=r"((r)[4]), "=r"((r)[5]), "=r"((r)[6]), "=r"((r)[7]), \
          "=r"((r)[8]), "=r"((r)[9]), "=r"((r)[10]), "=r"((r)[11]), "=r"((r)[12]), "=r"((r)[13]), "=r"((r)[14]), "=r"((r)[15]), \
          "=r"((r)[16]), "=r"((r)[17]), "=r"((r)[18]), "=r"((r)[19]), "=r"((r)[20]), "=r"((r)[21]), "=r"((r)[22]), "=r"((r)[23]), \
          "=r"((r)[24]), "=r"((r)[25]), "=r"((r)[26]), "=r"((r)[27]), "=r"((r)[28]), "=r"((r)[29]), "=r"((r)[30]), "=r"((r)[31]) \
        : "r"(ta))

static constexpr uint64_t DESC_SW128 =
    (uint64_t(2) << 61) | (uint64_t(1) << 46) | (uint64_t(64) << 32) | (uint64_t(1) << 16);
#define MAKE_SMEM_DESC(a) (DESC_SW128 | ((uint64_t)((a) >> 4) & 0x3FFF))

// cta_group::2 TMA: both CTAs issue; complete_tx to the LEADER's barrier.
__device__ __forceinline__ void tma_load_2d_cg2(uint32_t sa, const void* map, int x, int y, uint32_t mbar) {
    asm volatile(
        "{\n\t.reg .b32 lb;\n\tand.b32 lb, %4, 0xFEFFFFFF;\n\t"
        "cp.async.bulk.tensor.2d.cta_group::2.shared::cluster.global.tile.mbarrier::complete_tx::bytes "
        "[%0], [%1, {%2, %3}], [lb];\n\t}"
        :: "r"(sa), "l"(map), "r"(x), "r"(y), "r"(mbar) : "memory");
}
__device__ __forceinline__ void mma_f16_ss_cg2(uint32_t d, uint64_t ad, uint64_t bd, uint32_t idesc, bool acc) {
    uint32_t en = acc ? 1u : 0u, z = 0;
    asm volatile("{\n\t.reg .pred p;\n\tsetp.ne.u32 p, %5, 0;\n\t"
                 "tcgen05.mma.cta_group::2.kind::f16 [%0], %1, %2, %3, {%4, %4, %4, %4, %4, %4, %4, %4}, p;\n\t}"
                 :: "r"(d), "l"(ad), "l"(bd), "r"(idesc), "r"(z), "r"(en) : "memory");
}
#endif // HAS_TCGEN05

// ============ K0: W2 -> fp16 copy ============
__global__ void round_w2_kernel(const float* __restrict__ W2) {
    int i = blockIdx.x * 256 + threadIdx.x;   // grid covers VOCAB*INNER/2
    float2 v = ((const float2*)W2)[i];
    ((__half2*)g_W2r)[i] = __floats2half2_rn(v.x, v.y);
}

// ============ K1: P = enc@We^T + b1, Q = dec@Wd^T ============
__global__ void proj_kernel(const float* __restrict__ enc, const float* __restrict__ dec,
                            const float* __restrict__ W1, const float* __restrict__ b1) {
    __shared__ float As[16][68];
    __shared__ float Bs[16][68];
    const int bn = blockIdx.x, bm = blockIdx.y;
    const int tid = threadIdx.x, tx = tid & 15, ty = tid >> 4;
    const bool is_enc = (bm < 16);
    const float* Asrc = is_enc ? (enc + (size_t)bm * 64 * ENC_DIM)
                               : (dec + (size_t)(bm - 16) * 64 * ENC_DIM);
    const int koff = is_enc ? 0 : ENC_DIM;
    float acc[4][4];
#pragma unroll
    for (int i = 0; i < 4; i++)
#pragma unroll
        for (int j = 0; j < 4; j++) acc[i][j] = 0.f;

    for (int kt = 0; kt < 40; kt++) {
#pragma unroll
        for (int p = 0; p < 4; p++) {
            int idx = tid + p * 256, m = idx >> 4, k = idx & 15;
            As[k][m] = Asrc[(size_t)m * ENC_DIM + kt * 16 + k];
            Bs[k][m] = W1[(size_t)(bn * 64 + m) * 1280 + koff + kt * 16 + k];
        }
        __syncthreads();
#pragma unroll
        for (int kk = 0; kk < 16; kk++) {
            float4 a = *(const float4*)&As[kk][ty * 4];
            float4 b = *(const float4*)&Bs[kk][tx * 4];
            float av[4] = {a.x, a.y, a.z, a.w}, bv[4] = {b.x, b.y, b.z, b.w};
#pragma unroll
            for (int i = 0; i < 4; i++)
#pragma unroll
                for (int j = 0; j < 4; j++) acc[i][j] += av[i] * bv[j];
        }
        __syncthreads();
    }
    float bias[4] = {0.f, 0.f, 0.f, 0.f};
    if (is_enc) {
#pragma unroll
        for (int j = 0; j < 4; j++) bias[j] = b1[bn * 64 + tx * 4 + j];
    }
#pragma unroll
    for (int i = 0; i < 4; i++) {
        int mg = bm * 64 + ty * 4 + i;
        float* dst = (mg < BT) ? &g_P[(size_t)mg * INNER] : &g_Q[(size_t)(mg - BT) * INNER];
        *(float4*)&dst[bn * 64 + tx * 4] = make_float4(acc[i][0] + bias[0], acc[i][1] + bias[1],
                                                       acc[i][2] + bias[2], acc[i][3] + bias[3]);
    }
}

// ============ K2: H = fp16(tanh(P + Q)) ============
__global__ void h_kernel() {
    __shared__ float4 sPB[128];
    const int bt = blockIdx.x, b = bt >> 8;
    if (threadIdx.x < 128)
        sPB[threadIdx.x] = ((const float4*)(g_P + (size_t)bt * INNER))[threadIdx.x];
    __syncthreads();
    const float4* Qb = (const float4*)(g_Q + (size_t)b * 64 * INNER);
    uint2* Hrow = (uint2*)(g_H + (size_t)bt * 64 * INNER);
#pragma unroll 4
    for (int i = threadIdx.x; i < 64 * 128; i += 256) {
        const float4 p = sPB[i & 127];
        const float4 q = Qb[i];
        __half2 h0 = __floats2half2_rn(tanh_fast(p.x + q.x), tanh_fast(p.y + q.y));
        __half2 h1 = __floats2half2_rn(tanh_fast(p.z + q.z), tanh_fast(p.w + q.w));
        uint2 u;
        u.x = *(uint32_t*)&h0;
        u.y = *(uint32_t*)&h1;
        Hrow[i] = u;
    }
}

// ==== K3: cluster-2 cg2 fp16 GEMM, 256x128 tiles, 4-deep TMEM pipeline ======
static constexpr int KC = 64, NK = INNER / KC;           // 8 K-chunks per tile
static constexpr int STG = 4;                            // smem stages
static constexpr int NTMEM = 4;                          // TMEM accumulators (128 cols each)
static constexpr int TILES_N = VOCAB / 128;              // 16
static constexpr int TOTAL_TILES = (MROWS / 256) * TILES_N;  // 4096
static constexpr int NCLUST = 74;
static constexpr int TPC = (TOTAL_TILES + NCLUST - 1) / NCLUST;  // 56
static constexpr int THREADS = 192;
// kind::f16, fp16 in, fp32 accum, M=256 (cg2), N=128
static constexpr uint32_t IDESC_F16_CG2 =
    (1u << 4) | (16u << 17) | (16u << 24);

static constexpr int SM_TMEMP = 0;
static constexpr int SM_FULL  = 32;                     // full[s] = 32 + 16*s  (4)
static constexpr int SM_DONE  = 128;                    // done[s] = 128 + 16*s (4)
static constexpr int SM_FINB  = 224;                    // fin[b]  = 224 + 16*b (4)
static constexpr int SM_FREE  = 304;                    // free[b] = 304 + 16*b (4)
static constexpr int SM_A     = 4096;
static constexpr int A_BYTES  = 128 * KC * 2;           // 16 KB (128 A-rows/CTA)
static constexpr int B_BYTES  = 64 * KC * 2;            // 8 KB (64 B-rows/CTA, N=128 cg2)
static constexpr int SM_B     = SM_A + STG * A_BYTES;   // 69632
static constexpr int SMEM_SZ  = SM_B + STG * B_BYTES;   // 102400 (~100 KB)
static constexpr int TX_BYTES = 2 * (A_BYTES + B_BYTES);  // 48 KB (both CTAs)

__global__ void __launch_bounds__(THREADS, 1) __cluster_dims__(2, 1, 1) joint_gemm(
    const __grid_constant__ CUtensorMap tma_h,
    const __grid_constant__ CUtensorMap tma_w,
    const float* __restrict__ b2, float* __restrict__ out) {
    extern __shared__ __align__(1024) char smem[];
    const int tid = threadIdx.x;
    const int cid = blockIdx.x >> 1;
    const int first = cid * TPC;
    const int nt = min(TPC, TOTAL_TILES - first);
#if HAS_TCGEN05
    const uint32_t sb = smem_to_u32(smem);
    const int wid = tid >> 5, lid = tid & 31;
    const uint32_t rank = cluster_ctarank();

    if (tid == 0) {
#pragma unroll
        for (int s = 0; s < STG; s++) {
            MBARRIER_INIT(sb + SM_FULL + 16 * s, 1);   // complete_tx only
            MBARRIER_INIT(sb + SM_DONE + 16 * s, 1);   // commit mcast 0x3
        }
#pragma unroll
        for (int b = 0; b < NTMEM; b++) {
            MBARRIER_INIT(sb + SM_FINB + 16 * b, 1);
            MBARRIER_INIT(sb + SM_FREE + 16 * b, 2);   // both CTAs' epilogues
        }
    }
    if (wid == 0) { TCGEN05_ALLOC_CG2(sb + SM_TMEMP, 512); TCGEN05_RELINQ_CG2(); }
    __syncthreads();
    uint32_t tmem;
    asm volatile("ld.shared.b32 %0, [%1];" : "=r"(tmem) : "r"(sb + SM_TMEMP));
    CLUSTER_SYNC();   // peer barriers live before cg2 TMA / multicast commit

    const int gend = nt * NK;

    if (wid == 5) {
        // ===== producer (both CTAs, one elected thread) =====
        if (elect_one_pred()) {
            int dph[STG] = {0, 0, 0, 0};
            for (int g = 0; g < gend; g++) {
                const int s = g & (STG - 1);
                if (g >= STG) { MBARRIER_WAIT_PARITY_RELAXED(sb + SM_DONE + 16 * s, dph[s]); dph[s] ^= 1; }
                const int t = first + (g >> 3);
                const int kc = g & 7;
                const int nn = t & 15, mt = t >> 4;
                const uint32_t full = sb + SM_FULL + 16 * s;
                if (rank == 0) MBARRIER_EXPECT_TX(full, TX_BYTES);
                tma_load_2d_cg2(sb + SM_A + s * A_BYTES, &tma_h, kc * KC, mt * 256 + (int)rank * 128, full);
                tma_load_2d_cg2(sb + SM_B + s * B_BYTES, &tma_w, kc * KC, nn * 128 + (int)rank * 64, full);
            }
        }
    } else if (wid == 4) {
        // ===== MMA issuer (leader CTA only, one elected thread) =====
        if (rank == 0 && elect_one_pred()) {
            int fph[STG] = {0, 0, 0, 0};
            int frph[NTMEM] = {0, 0, 0, 0};
            for (int ti = 0; ti < nt; ti++) {
                const int b = ti & (NTMEM - 1);
                if (ti >= NTMEM) { MBARRIER_WAIT_PARITY(sb + SM_FREE + 16 * b, frph[b]); frph[b] ^= 1; }
                const uint32_t dbuf = tmem + b * 128;
                for (int kc = 0; kc < NK; kc++) {
                    const int s = (ti * NK + kc) & (STG - 1);
                    MBARRIER_WAIT_PARITY_RELAXED(sb + SM_FULL + 16 * s, fph[s]); fph[s] ^= 1;
                    const uint64_t ad = MAKE_SMEM_DESC(sb + SM_A + s * A_BYTES);
                    const uint64_t bd = MAKE_SMEM_DESC(sb + SM_B + s * B_BYTES);
#pragma unroll
                    for (int j = 0; j < 4; j++)   // K=16 fp16 = 32B = 2 desc units
                        mma_f16_ss_cg2(dbuf, ad + 2 * j, bd + 2 * j, IDESC_F16_CG2, (kc | j) != 0);
                    TCGEN05_COMMIT_MC_CG2(sb + SM_DONE + 16 * s, 0x3);
                }
                TCGEN05_COMMIT_MC_CG2(sb + SM_FINB + 16 * b, 0x3);
            }
        }
    } else {
        // ===== epilogue (warps 0-3, both CTAs) =====
        const float4* b2v = (const float4*)b2;
        int finph[NTMEM] = {0, 0, 0, 0};
        for (int ti = 0; ti < nt; ti++) {
            const int b = ti & (NTMEM - 1);
            MBARRIER_WAIT_PARITY(sb + SM_FINB + 16 * b, finph[b]); finph[b] ^= 1;
            TCGEN05_FENCE_AFTER();
            const int t = first + ti;
            const int nn = t & 15, mt = t >> 4;
            const int row = mt * 256 + (int)rank * 128 + wid * 32 + lid;
            float4* orow = (float4*)(out + (size_t)row * VOCAB + nn * 128);
            const uint32_t dbuf = tmem + b * 128;
#pragma unroll 1
            for (int ch = 0; ch < 4; ch += 2) {       // pairwise LDTM
                uint32_t r0[32], r1[32];
                TCGEN05_LD_X32(r0, dbuf + ch * 32);
                TCGEN05_LD_X32(r1, dbuf + (ch + 1) * 32);
                TCGEN05_WAIT_LD();
#pragma unroll
                for (int j = 0; j < 8; j++) {
                    float4 bb = b2v[nn * 32 + ch * 8 + j];
                    float4 v;
                    v.x = __uint_as_float(r0[j * 4 + 0]) + bb.x;
                    v.y = __uint_as_float(r0[j * 4 + 1]) + bb.y;
                    v.z = __uint_as_float(r0[j * 4 + 2]) + bb.z;
                    v.w = __uint_as_float(r0[j * 4 + 3]) + bb.w;
                    orow[ch * 8 + j] = v;
                }
#pragma unroll
                for (int j = 0; j < 8; j++) {
                    float4 bb = b2v[nn * 32 + (ch + 1) * 8 + j];
                    float4 v;
                    v.x = __uint_as_float(r1[j * 4 + 0]) + bb.x;
                    v.y = __uint_as_float(r1[j * 4 + 1]) + bb.y;
                    v.z = __uint_as_float(r1[j * 4 + 2]) + bb.z;
                    v.w = __uint_as_float(r1[j * 4 + 3]) + bb.w;
                    orow[(ch + 1) * 8 + j] = v;
                }
            }
            TCGEN05_FENCE_BEFORE();
            asm volatile("bar.sync 1, 128;" ::: "memory");   // warps 0-3 of this CTA
            if (tid == 0) MBARRIER_ARRIVE_LEADER(sb + SM_FREE + 16 * b);
        }
    }

    __syncthreads();
    if (wid == 0) TCGEN05_DEALLOC_CG2(tmem, 512);
    CLUSTER_SYNC();
#else
    // SIMT fallback (non-'a' target only): correct, never selected on GB300.
    (void)tma_h; (void)tma_w;
    const int rank = blockIdx.x & 1;
    for (int ti = 0; ti < nt; ti++) {
        const int t = first + ti;
        const int nn = t & 15, mt = t >> 4;
        for (int e = tid; e < 128 * 128; e += THREADS) {
            const int r = e >> 7, c = e & 127;
            const int row = mt * 256 + rank * 128 + r;
            const __half* Ar = &g_H[(size_t)row * INNER];
            const __half* Br = &g_W2r[(size_t)(nn * 128 + c) * INNER];
            float acc = 0.f;
            for (int k = 0; k < INNER; k++) acc += __half2float(Ar[k]) * __half2float(Br[k]);
            out[(size_t)row * VOCAB + nn * 128 + c] = acc + b2[nn * 128 + c];
        }
    }
#endif
}

// ============ host ============
typedef CUresult (*PFN_encodeTiled)(
    CUtensorMap*, CUtensorMapDataType, cuuint32_t, void*,
    const cuuint64_t*, const cuuint64_t*, const cuuint32_t*, const cuuint32_t*,
    CUtensorMapInterleave, CUtensorMapSwizzle, CUtensorMapL2promotion, CUtensorMapFloatOOBfill);

static void make_map_f16(PFN_encodeTiled fn, CUtensorMap* m, void* ptr,
                         uint64_t d0, uint64_t d1, uint32_t b0, uint32_t b1) {
    cuuint64_t dims[2] = {d0, d1};
    cuuint64_t strides[1] = {d0 * 2};
    cuuint32_t box[2] = {b0, b1};
    cuuint32_t es[2] = {1, 1};
    fn(m, CU_TENSOR_MAP_DATA_TYPE_FLOAT16, 2, ptr, dims, strides, box, es,
       CU_TENSOR_MAP_INTERLEAVE_NONE, CU_TENSOR_MAP_SWIZZLE_128B,
       CU_TENSOR_MAP_L2_PROMOTION_L2_128B, CU_TENSOR_MAP_FLOAT_OOB_FILL_NONE);
}

extern "C" void kernel_launch(void* const* d_in, const int* in_sizes, int n_in,
                              void* d_out, int out_size) {
    const float* enc = (const float*)d_in[0];
    const float* dec = (const float*)d_in[1];
    const float* W1  = (const float*)d_in[2];
    const float* b1  = (const float*)d_in[3];
    const float* W2  = (const float*)d_in[4];
    const float* b2  = (const float*)d_in[5];
    float* out = (float*)d_out;

    void* hptr = nullptr; cudaGetSymbolAddress(&hptr, g_H);
    void* wptr = nullptr; cudaGetSymbolAddress(&wptr, g_W2r);

    PFN_encodeTiled enc_fn = nullptr;
    cudaDriverEntryPointQueryResult st;
    cudaGetDriverEntryPointByVersion("cuTensorMapEncodeTiled", (void**)&enc_fn, 12050,
                                     cudaEnableDefault, &st);
    CUtensorMap mapH, mapW;
    make_map_f16(enc_fn, &mapH, hptr, INNER, MROWS, KC, 128);
    make_map_f16(enc_fn, &mapW, wptr, INNER, VOCAB, KC, 64);

    cudaFuncSetAttribute(joint_gemm, cudaFuncAttributeMaxDynamicSharedMemorySize, SMEM_SZ);

    round_w2_kernel<<<VOCAB * INNER / 512, 256>>>(W2);
    proj_kernel<<<dim3(8, 20), 256>>>(enc, dec, W1, b1);
    h_kernel<<<BT, 256>>>();
    joint_gemm<<<NCLUST * 2, THREADS, SMEM_SZ>>>(mapH, mapW, b2, out);
}

// round 17
// speedup vs baseline: 1.5669x; 1.0437x over previous
#include <cuda_runtime.h>
#include <cuda.h>
#include <cuda_bf16.h>
#include <cuda_fp16.h>
#include <cstdint>

static constexpr int ENC_DIM = 640;
static constexpr int INNER   = 512;
static constexpr int VOCAB   = 2048;
static constexpr int BT      = 1024;
static constexpr int MROWS   = 65536;

__device__ float  g_P[BT * INNER];     // enc_proj + b1
__device__ float  g_Q[256 * INNER];    // dec_proj
__device__ __half g_H[(size_t)MROWS * INNER];   // tanh(...) in fp16 (67 MB)
__device__ __half g_W2r[VOCAB * INNER];         // W2 in fp16 (2 MB)

#if !defined(__CUDA_ARCH__) || defined(__CUDA_ARCH_FEAT_SM103_ALL) || defined(__CUDA_ARCH_FEAT_SM100_ALL) || defined(__CUDA_ARCH_FEAT_SM101_ALL)
#define HAS_TCGEN05 1
#else
#define HAS_TCGEN05 0
#endif

__device__ __forceinline__ uint32_t smem_to_u32(const void* ptr) {
    uint32_t a;
    asm("{ .reg .u64 t; cvta.to.shared.u64 t, %1; cvt.u32.u64 %0, t; }" : "=r"(a) : "l"(ptr));
    return a;
}
__device__ __forceinline__ float tanh_fast(float x) {
    float y;
    asm("tanh.approx.f32 %0, %1;" : "=f"(y) : "f"(x));
    return y;
}

#if HAS_TCGEN05
__device__ __forceinline__ uint32_t elect_one_pred() {
    uint32_t p;
    asm volatile("{\n\t.reg .pred p;\n\telect.sync _|p, 0xFFFFFFFF;\n\tselp.b32 %0, 1, 0, p;\n\t}" : "=r"(p));
    return p;
}
__device__ __forceinline__ uint32_t cluster_ctarank() {
    uint32_t r;
    asm("mov.u32 %0, %%cluster_ctarank;" : "=r"(r));
    return r;
}
#define MBARRIER_INIT(m, c) \
    asm volatile("mbarrier.init.shared.b64 [%0], %1;" :: "r"((uint32_t)(m)), "r"((uint32_t)(c)) : "memory")
#define MBARRIER_EXPECT_TX(m, b) \
    asm volatile("mbarrier.arrive.expect_tx.shared.b64 _, [%0], %1;" :: "r"((uint32_t)(m)), "r"((uint32_t)(b)) : "memory")
// arrive on the LEADER CTA's barrier at same offset (clear bit 24)
#define MBARRIER_ARRIVE_LEADER(m) \
    asm volatile("{\n\t.reg .b32 a;\n\tand.b32 a, %0, 0xFEFFFFFF;\n\tmbarrier.arrive.shared::cluster.b64 _, [a];\n\t}" \
        :: "r"((uint32_t)(m)) : "memory")

#define MBAR_WAIT(m, ph, SEM) do { \
    uint32_t _m = (uint32_t)(m); uint32_t _p = (uint32_t)(ph); uint32_t _d; \
    asm volatile("{\n\t.reg .pred p;\n\tmbarrier.try_wait.parity." SEM ".cta.shared::cta.b64 p, [%1], %2;\n\tselp.b32 %0, 1, 0, p;\n\t}" \
        : "=r"(_d) : "r"(_m), "r"(_p) : "memory"); \
    if (!_d) { \
        asm volatile("{\n\t.reg .pred P1;\n\tWL_%=:\n\tmbarrier.try_wait.parity." SEM ".cta.shared::cta.b64 P1, [%0], %1, 0x989680;\n\t@P1 bra.uni WD_%=;\n\tbra.uni WL_%=;\n\tWD_%=:\n\t}" \
            :: "r"(_m), "r"(_p) : "memory"); \
    } } while(0)
#define MBARRIER_WAIT_PARITY(m, p)          MBAR_WAIT(m, p, "acquire")
#define MBARRIER_WAIT_PARITY_RELAXED(m, p)  MBAR_WAIT(m, p, "relaxed")

#define TCGEN05_ALLOC_CG2(sa, n) \
    asm volatile("tcgen05.alloc.cta_group::2.sync.aligned.shared::cta.b32 [%0], %1;" :: "r"((uint32_t)(sa)), "r"((uint32_t)(n)) : "memory")
#define TCGEN05_DEALLOC_CG2(t, n) \
    asm volatile("tcgen05.dealloc.cta_group::2.sync.aligned.b32 %0, %1;" :: "r"(t), "r"((uint32_t)(n)))
#define TCGEN05_RELINQ_CG2() \
    asm volatile("tcgen05.relinquish_alloc_permit.cta_group::2.sync.aligned;")
#define TCGEN05_COMMIT_MC_CG2(m, mask) \
    asm volatile("tcgen05.commit.cta_group::2.mbarrier::arrive::one.shared::cluster.multicast::cluster.b64 [%0], %1;" \
        :: "r"((uint32_t)(m)), "h"((uint16_t)(mask)) : "memory")
#define TCGEN05_WAIT_LD()      asm volatile("tcgen05.wait::ld.sync.aligned;" ::: "memory")
#define TCGEN05_FENCE_AFTER()  asm volatile("tcgen05.fence::after_thread_sync;" ::: "memory")
#define TCGEN05_FENCE_BEFORE() asm volatile("tcgen05.fence::before_thread_sync;" ::: "memory")
#define CLUSTER_SYNC() do { \
    asm volatile("barrier.cluster.arrive.aligned;" ::: "memory"); \
    asm volatile("barrier.cluster.wait.aligned;" ::: "memory"); } while(0)

#define TCGEN05_LD_X32(r, ta) \
    asm volatile("tcgen05.ld.sync.aligned.32x32b.x32.b32 " \
        "{%0, %1, %2, %3, %4, %5, %6, %7, %8, %9, %10, %11, %12, %13, %14, %15, " \
        " %16, %17, %18, %19, %20, %21, %22, %23, %24, %25, %26, %27, %28, %29, %30, %31}, [%32];" \
        : "=r"((r)[0]), "=r"((r)[1]), "=r"((r)[2]), "=r"((r)[3]), "=r"((r)[4]), "=r"((r)[5]), "=r"((r)[6]), "=r"((r)[7]), \
          "=r"((r)[8]), "=r"((r)[9]), "=r"((r)[10]), "=r"((r)[11]), "=r"((r)[12]), "=r"((r)[13]), "=r"((r)[14]), "=r"((r)[15]), \
          "=r"((r)[16]), "=r"((r)[17]), "=r"((r)[18]), "=r"((r)[19]), "=r"((r)[20]), "=r"((r)[21]), "=r"((r)[22]), "=r"((r)[23]), \
          "=r"((r)[24]), "=r"((r)[25]), "=r"((r)[26]), "=r"((r)[27]), "=r"((r)[28]), "=r"((r)[29]), "=r"((r)[30]), "=r"((r)[31]) \
        : "r"(ta))

static constexpr uint64_t DESC_SW128 =
    (uint64_t(2) << 61) | (uint64_t(1) << 46) | (uint64_t(64) << 32) | (uint64_t(1) << 16);
#define MAKE_SMEM_DESC(a) (DESC_SW128 | ((uint64_t)((a) >> 4) & 0x3FFF))

// cta_group::2 TMA: both CTAs issue; complete_tx to the LEADER's barrier.
__device__ __forceinline__ void tma_load_2d_cg2(uint32_t sa, const void* map, int x, int y, uint32_t mbar) {
    asm volatile(
        "{\n\t.reg .b32 lb;\n\tand.b32 lb, %4, 0xFEFFFFFF;\n\t"
        "cp.async.bulk.tensor.2d.cta_group::2.shared::cluster.global.tile.mbarrier::complete_tx::bytes "
        "[%0], [%1, {%2, %3}], [lb];\n\t}"
        :: "r"(sa), "l"(map), "r"(x), "r"(y), "r"(mbar) : "memory");
}
__device__ __forceinline__ void mma_f16_ss_cg2(uint32_t d, uint64_t ad, uint64_t bd, uint32_t idesc, bool acc) {
    uint32_t en = acc ? 1u : 0u, z = 0;
    asm volatile("{\n\t.reg .pred p;\n\tsetp.ne.u32 p, %5, 0;\n\t"
                 "tcgen05.mma.cta_group::2.kind::f16 [%0], %1, %2, %3, {%4, %4, %4, %4, %4, %4, %4, %4}, p;\n\t}"
                 :: "r"(d), "l"(ad), "l"(bd), "r"(idesc), "r"(z), "r"(en) : "memory");
}
#endif // HAS_TCGEN05

// ============ K0: W2 -> fp16 copy ============
__global__ void round_w2_kernel(const float* __restrict__ W2) {
    int i = blockIdx.x * 256 + threadIdx.x;   // grid covers VOCAB*INNER/2
    float2 v = ((const float2*)W2)[i];
    ((__half2*)g_W2r)[i] = __floats2half2_rn(v.x, v.y);
}

// ============ K1: P = enc@We^T + b1, Q = dec@Wd^T ============
__global__ void proj_kernel(const float* __restrict__ enc, const float* __restrict__ dec,
                            const float* __restrict__ W1, const float* __restrict__ b1) {
    __shared__ float As[16][68];
    __shared__ float Bs[16][68];
    const int bn = blockIdx.x, bm = blockIdx.y;
    const int tid = threadIdx.x, tx = tid & 15, ty = tid >> 4;
    const bool is_enc = (bm < 16);
    const float* Asrc = is_enc ? (enc + (size_t)bm * 64 * ENC_DIM)
                               : (dec + (size_t)(bm - 16) * 64 * ENC_DIM);
    const int koff = is_enc ? 0 : ENC_DIM;
    float acc[4][4];
#pragma unroll
    for (int i = 0; i < 4; i++)
#pragma unroll
        for (int j = 0; j < 4; j++) acc[i][j] = 0.f;

    for (int kt = 0; kt < 40; kt++) {
#pragma unroll
        for (int p = 0; p < 4; p++) {
            int idx = tid + p * 256, m = idx >> 4, k = idx & 15;
            As[k][m] = Asrc[(size_t)m * ENC_DIM + kt * 16 + k];
            Bs[k][m] = W1[(size_t)(bn * 64 + m) * 1280 + koff + kt * 16 + k];
        }
        __syncthreads();
#pragma unroll
        for (int kk = 0; kk < 16; kk++) {
            float4 a = *(const float4*)&As[kk][ty * 4];
            float4 b = *(const float4*)&Bs[kk][tx * 4];
            float av[4] = {a.x, a.y, a.z, a.w}, bv[4] = {b.x, b.y, b.z, b.w};
#pragma unroll
            for (int i = 0; i < 4; i++)
#pragma unroll
                for (int j = 0; j < 4; j++) acc[i][j] += av[i] * bv[j];
        }
        __syncthreads();
    }
    float bias[4] = {0.f, 0.f, 0.f, 0.f};
    if (is_enc) {
#pragma unroll
        for (int j = 0; j < 4; j++) bias[j] = b1[bn * 64 + tx * 4 + j];
    }
#pragma unroll
    for (int i = 0; i < 4; i++) {
        int mg = bm * 64 + ty * 4 + i;
        float* dst = (mg < BT) ? &g_P[(size_t)mg * INNER] : &g_Q[(size_t)(mg - BT) * INNER];
        *(float4*)&dst[bn * 64 + tx * 4] = make_float4(acc[i][0] + bias[0], acc[i][1] + bias[1],
                                                       acc[i][2] + bias[2], acc[i][3] + bias[3]);
    }
}

// ============ K2: H = fp16(tanh(P + Q)) ============
__global__ void h_kernel() {
    __shared__ float4 sPB[128];
    const int bt = blockIdx.x, b = bt >> 8;
    if (threadIdx.x < 128)
        sPB[threadIdx.x] = ((const float4*)(g_P + (size_t)bt * INNER))[threadIdx.x];
    __syncthreads();
    const float4* Qb = (const float4*)(g_Q + (size_t)b * 64 * INNER);
    uint2* Hrow = (uint2*)(g_H + (size_t)bt * 64 * INNER);
#pragma unroll 4
    for (int i = threadIdx.x; i < 64 * 128; i += 256) {
        const float4 p = sPB[i & 127];
        const float4 q = Qb[i];
        __half2 h0 = __floats2half2_rn(tanh_fast(p.x + q.x), tanh_fast(p.y + q.y));
        __half2 h1 = __floats2half2_rn(tanh_fast(p.z + q.z), tanh_fast(p.w + q.w));
        uint2 u;
        u.x = *(uint32_t*)&h0;
        u.y = *(uint32_t*)&h1;
        Hrow[i] = u;
    }
}

// ==== K3: cluster-2 cg2 fp16 GEMM; n-tile PAIRS share A; 4 TMEM buffers ======
static constexpr int KC = 64, NK = INNER / KC;           // 8 K-chunks per pair
static constexpr int STG = 4;                            // smem stages
static constexpr int NPAIR_N = VOCAB / 256;              // 8 n-pairs
static constexpr int NP_TOTAL = (MROWS / 256) * NPAIR_N; // 2048 pairs
static constexpr int NCLUST = 74;
static constexpr int TPC = (NP_TOTAL + NCLUST - 1) / NCLUST;  // 28
static constexpr int THREADS = 192;
// kind::f16, fp16 in, fp32 accum, M=256 (cg2), N=128 per MMA
static constexpr uint32_t IDESC_F16_CG2 =
    (1u << 4) | (16u << 17) | (16u << 24);

static constexpr int SM_TMEMP = 0;
static constexpr int SM_FULL  = 32;                     // full[s] = 32 + 16*s  (4)
static constexpr int SM_DONE  = 128;                    // done[s] = 128 + 16*s (4)
static constexpr int SM_FINB  = 224;                    // fin[p]  = 224 + 16*p (2)
static constexpr int SM_FREE  = 272;                    // free[p] = 272 + 16*p (2)
static constexpr int SM_A     = 4096;
static constexpr int A_BYTES  = 128 * KC * 2;           // 16 KB (128 A-rows/CTA)
static constexpr int B_BYTES  = 64 * KC * 2;            // 8 KB per n-tile (64 rows/CTA)
static constexpr int STAGE_SZ = A_BYTES + 2 * B_BYTES;  // 32 KB
static constexpr int SMEM_SZ  = SM_A + STG * STAGE_SZ;  // 135168
static constexpr int TX_BYTES = 2 * STAGE_SZ;           // 64 KB (both CTAs)

__global__ void __launch_bounds__(THREADS, 1) __cluster_dims__(2, 1, 1) joint_gemm(
    const __grid_constant__ CUtensorMap tma_h,
    const __grid_constant__ CUtensorMap tma_w,
    const float* __restrict__ b2, float* __restrict__ out) {
    extern __shared__ __align__(1024) char smem[];
    const int tid = threadIdx.x;
    const int cid = blockIdx.x >> 1;
    const int first = cid * TPC;
    const int nt = min(TPC, NP_TOTAL - first);
#if HAS_TCGEN05
    const uint32_t sb = smem_to_u32(smem);
    const int wid = tid >> 5, lid = tid & 31;
    const uint32_t rank = cluster_ctarank();

    if (tid == 0) {
#pragma unroll
        for (int s = 0; s < STG; s++) {
            MBARRIER_INIT(sb + SM_FULL + 16 * s, 1);   // complete_tx only
            MBARRIER_INIT(sb + SM_DONE + 16 * s, 1);   // commit mcast 0x3
        }
#pragma unroll
        for (int p = 0; p < 2; p++) {
            MBARRIER_INIT(sb + SM_FINB + 16 * p, 1);
            MBARRIER_INIT(sb + SM_FREE + 16 * p, 2);   // both CTAs' epilogues
        }
    }
    if (wid == 0) { TCGEN05_ALLOC_CG2(sb + SM_TMEMP, 512); TCGEN05_RELINQ_CG2(); }
    __syncthreads();
    uint32_t tmem;
    asm volatile("ld.shared.b32 %0, [%1];" : "=r"(tmem) : "r"(sb + SM_TMEMP));
    CLUSTER_SYNC();   // peer barriers live before cg2 TMA / multicast commit

    const int gend = nt * NK;

    if (wid == 5) {
        // ===== producer (both CTAs, one elected thread) =====
        if (elect_one_pred()) {
            int dph[STG] = {0, 0, 0, 0};
            for (int g = 0; g < gend; g++) {
                const int s = g & (STG - 1);
                if (g >= STG) { MBARRIER_WAIT_PARITY_RELAXED(sb + SM_DONE + 16 * s, dph[s]); dph[s] ^= 1; }
                const int t = first + (g >> 3);
                const int kc = g & 7;
                const int np = t & 7, mt = t >> 3;
                const uint32_t full = sb + SM_FULL + 16 * s;
                const uint32_t stg = sb + SM_A + s * STAGE_SZ;
                if (rank == 0) MBARRIER_EXPECT_TX(full, TX_BYTES);
                tma_load_2d_cg2(stg, &tma_h, kc * KC, mt * 256 + (int)rank * 128, full);
                tma_load_2d_cg2(stg + A_BYTES,           &tma_w, kc * KC, (np * 2) * 128 + (int)rank * 64, full);
                tma_load_2d_cg2(stg + A_BYTES + B_BYTES, &tma_w, kc * KC, (np * 2 + 1) * 128 + (int)rank * 64, full);
            }
        }
    } else if (wid == 4) {
        // ===== MMA issuer (leader CTA only, one elected thread) =====
        if (rank == 0 && elect_one_pred()) {
            int fph[STG] = {0, 0, 0, 0};
            int frph[2] = {0, 0};
            for (int ti = 0; ti < nt; ti++) {
                const int ps = ti & 1;                // pair slot
                if (ti >= 2) { MBARRIER_WAIT_PARITY(sb + SM_FREE + 16 * ps, frph[ps]); frph[ps] ^= 1; }
                const uint32_t dbuf0 = tmem + ps * 256;
                for (int kc = 0; kc < NK; kc++) {
                    const int s = (ti * NK + kc) & (STG - 1);
                    MBARRIER_WAIT_PARITY_RELAXED(sb + SM_FULL + 16 * s, fph[s]); fph[s] ^= 1;
                    const uint32_t stg = sb + SM_A + s * STAGE_SZ;
                    const uint64_t ad = MAKE_SMEM_DESC(stg);
#pragma unroll
                    for (int h = 0; h < 2; h++) {
                        const uint64_t bd = MAKE_SMEM_DESC(stg + A_BYTES + h * B_BYTES);
#pragma unroll
                        for (int j = 0; j < 4; j++)   // K=16 fp16 = 32B = 2 desc units
                            mma_f16_ss_cg2(dbuf0 + h * 128, ad + 2 * j, bd + 2 * j,
                                           IDESC_F16_CG2, (kc | j) != 0);
                    }
                    TCGEN05_COMMIT_MC_CG2(sb + SM_DONE + 16 * s, 0x3);
                }
                TCGEN05_COMMIT_MC_CG2(sb + SM_FINB + 16 * ps, 0x3);
            }
        }
    } else {
        // ===== epilogue (warps 0-3, both CTAs) =====
        const float4* b2v = (const float4*)b2;
        int finph[2] = {0, 0};
        for (int ti = 0; ti < nt; ti++) {
            const int ps = ti & 1;
            MBARRIER_WAIT_PARITY(sb + SM_FINB + 16 * ps, finph[ps]); finph[ps] ^= 1;
            TCGEN05_FENCE_AFTER();
            const int t = first + ti;
            const int np = t & 7, mt = t >> 3;
            const int row = mt * 256 + (int)rank * 128 + wid * 32 + lid;
#pragma unroll
            for (int h = 0; h < 2; h++) {
                const int nn = np * 2 + h;
                float4* orow = (float4*)(out + (size_t)row * VOCAB + nn * 128);
                const uint32_t dbuf = tmem + ps * 256 + h * 128;
#pragma unroll 1
                for (int ch = 0; ch < 4; ch += 2) {   // pairwise LDTM
                    uint32_t r0[32], r1[32];
                    TCGEN05_LD_X32(r0, dbuf + ch * 32);
                    TCGEN05_LD_X32(r1, dbuf + (ch + 1) * 32);
                    TCGEN05_WAIT_LD();
#pragma unroll
                    for (int j = 0; j < 8; j++) {
                        float4 bb = b2v[nn * 32 + ch * 8 + j];
                        float4 v;
                        v.x = __uint_as_float(r0[j * 4 + 0]) + bb.x;
                        v.y = __uint_as_float(r0[j * 4 + 1]) + bb.y;
                        v.z = __uint_as_float(r0[j * 4 + 2]) + bb.z;
                        v.w = __uint_as_float(r0[j * 4 + 3]) + bb.w;
                        orow[ch * 8 + j] = v;
                    }
#pragma unroll
                    for (int j = 0; j < 8; j++) {
                        float4 bb = b2v[nn * 32 + (ch + 1) * 8 + j];
                        float4 v;
                        v.x = __uint_as_float(r1[j * 4 + 0]) + bb.x;
                        v.y = __uint_as_float(r1[j * 4 + 1]) + bb.y;
                        v.z = __uint_as_float(r1[j * 4 + 2]) + bb.z;
                        v.w = __uint_as_float(r1[j * 4 + 3]) + bb.w;
                        orow[(ch + 1) * 8 + j] = v;
                    }
                }
            }
            TCGEN05_FENCE_BEFORE();
            asm volatile("bar.sync 1, 128;" ::: "memory");   // warps 0-3 of this CTA
            if (tid == 0) MBARRIER_ARRIVE_LEADER(sb + SM_FREE + 16 * ps);
        }
    }

    __syncthreads();
    if (wid == 0) TCGEN05_DEALLOC_CG2(tmem, 512);
    CLUSTER_SYNC();
#else
    // SIMT fallback (non-'a' target only): correct, never selected on GB300.
    (void)tma_h; (void)tma_w;
    const int rank = blockIdx.x & 1;
    for (int ti = 0; ti < nt; ti++) {
        const int t = first + ti;
        const int np = t & 7, mt = t >> 3;
        for (int e = tid; e < 128 * 256; e += THREADS) {
            const int r = e >> 8, c = e & 255;
            const int row = mt * 256 + rank * 128 + r;
            const __half* Ar = &g_H[(size_t)row * INNER];
            const __half* Br = &g_W2r[(size_t)(np * 256 + c) * INNER];
            float acc = 0.f;
            for (int k = 0; k < INNER; k++) acc += __half2float(Ar[k]) * __half2float(Br[k]);
            out[(size_t)row * VOCAB + np * 256 + c] = acc + b2[np * 256 + c];
        }
    }
#endif
}

// ============ host ============
typedef CUresult (*PFN_encodeTiled)(
    CUtensorMap*, CUtensorMapDataType, cuuint32_t, void*,
    const cuuint64_t*, const cuuint64_t*, const cuuint32_t*, const cuuint32_t*,
    CUtensorMapInterleave, CUtensorMapSwizzle, CUtensorMapL2promotion, CUtensorMapFloatOOBfill);

static void make_map_f16(PFN_encodeTiled fn, CUtensorMap* m, void* ptr,
                         uint64_t d0, uint64_t d1, uint32_t b0, uint32_t b1) {
    cuuint64_t dims[2] = {d0, d1};
    cuuint64_t strides[1] = {d0 * 2};
    cuuint32_t box[2] = {b0, b1};
    cuuint32_t es[2] = {1, 1};
    fn(m, CU_TENSOR_MAP_DATA_TYPE_FLOAT16, 2, ptr, dims, strides, box, es,
       CU_TENSOR_MAP_INTERLEAVE_NONE, CU_TENSOR_MAP_SWIZZLE_128B,
       CU_TENSOR_MAP_L2_PROMOTION_L2_128B, CU_TENSOR_MAP_FLOAT_OOB_FILL_NONE);
}

extern "C" void kernel_launch(void* const* d_in, const int* in_sizes, int n_in,
                              void* d_out, int out_size) {
    const float* enc = (const float*)d_in[0];
    const float* dec = (const float*)d_in[1];
    const float* W1  = (const float*)d_in[2];
    const float* b1  = (const float*)d_in[3];
    const float* W2  = (const float*)d_in[4];
    const float* b2  = (const float*)d_in[5];
    float* out = (float*)d_out;

    void* hptr = nullptr; cudaGetSymbolAddress(&hptr, g_H);
    void* wptr = nullptr; cudaGetSymbolAddress(&wptr, g_W2r);

    PFN_encodeTiled enc_fn = nullptr;
    cudaDriverEntryPointQueryResult st;
    cudaGetDriverEntryPointByVersion("cuTensorMapEncodeTiled", (void**)&enc_fn, 12050,
                                     cudaEnableDefault, &st);
    CUtensorMap mapH, mapW;
    make_map_f16(enc_fn, &mapH, hptr, INNER, MROWS, KC, 128);
    make_map_f16(enc_fn, &mapW, wptr, INNER, VOCAB, KC, 64);

    cudaFuncSetAttribute(joint_gemm, cudaFuncAttributeMaxDynamicSharedMemorySize, SMEM_SZ);

    round_w2_kernel<<<VOCAB * INNER / 512, 256>>>(W2);
    proj_kernel<<<dim3(8, 20), 256>>>(enc, dec, W1, b1);
    h_kernel<<<BT, 256>>>();
    joint_gemm<<<NCLUST * 2, THREADS, SMEM_SZ>>>(mapH, mapW, b2, out);
}